// round 9
// baseline (speedup 1.0000x reference)
#include <cuda_runtime.h>

// MakeCutouts: 32 cutouts of x[8,3,512,512] fp32, adaptive-avg-pool (torch
// bins) to 224x224. Output [256, 3, 224, 224] fp32.
//
// Block = (cut, plane, super-group of 4 y-groups of 8 rows each). Per group:
//   Phase 1: half 0 (threads 0-127) bins 0-3, half 1 bins 4-7; consecutive
//            bins per half with the <=1-row overlap carried in registers;
//            float4 loads aligned-down from ox.
//   Phase 2: 224 threads x 8 rows (row pairs for LDS latency overlap).
// MAXTAP template: sz<=448 -> all bins span <=3 pixels (uniform branch).
// Block setup (x-bin metadata, lane constants, cut metadata) amortized over
// 32 output rows.

#define OUTS   224
#define BATCH  8
#define CHAN   3
#define HW     512
#define CUTN   32
#define NPLANE (BATCH * CHAN)   // 24
#define YG     8
#define NYG    (OUTS / YG)      // 28
#define GPB    4                // y-groups per block
#define NSG    (NYG / GPB)      // 7
#define BPH    4
#define CSTRIDE 520

__device__ __forceinline__ float inv_small(int n) {
    return n == 1 ? 1.0f : (n == 2 ? 0.5f : (n == 3 ? (1.0f / 3.0f) : 0.25f));
}
__device__ __forceinline__ void f4add(float4& a, const float4 b) {
    a.x += b.x; a.y += b.y; a.z += b.z; a.w += b.w;
}

struct Smem {
    float buf[YG][CSTRIDE];
    int   syny[2][YG];
    float invy[2][YG];
};

template<int MAXTAP>
__device__ __forceinline__ void run_groups(
    Smem* sm, const float* pbase, float* __restrict__ out,
    int sz, int shift, int span, int sg, int tid,
    int sx, int nx, float invx, long long obase)
{
    const int lane = tid & 127;
    const int half = tid >> 7;
    const int rem  = span - lane * 4;
    const int col4 = lane * 4;
    const int off  = shift + sx;
    const bool nx2 = nx > 1, nx3 = nx > 2, nx4 = nx > 3;

    #pragma unroll 1
    for (int g = 0; g < GPB; g++) {
        const int y0 = (sg * GPB + g) * YG;
        const int pg = g & 1;

        if (tid < YG) {
            const int y  = y0 + tid;
            const int sy = (y * sz) / OUTS;
            const int ny = ((y + 1) * sz + (OUTS - 1)) / OUTS - sy;
            sm->syny[pg][tid] = sy | (ny << 16);
            sm->invy[pg][tid] = inv_small(ny);
        }
        __syncthreads();

        // ---- Phase 1 ----
        if (rem >= 4) {
            float4 last; int pe = -1000;
            #pragma unroll
            for (int j = 0; j < BPH; j++) {
                const int m  = sm->syny[pg][half * BPH + j];
                const int sy = m & 0xFFFF;
                const int ny = m >> 16;
                const float* rp = pbase + (long long)sy * HW + col4;

                float4 acc, l;
                if (sy == pe - 1) { acc = last; l = last; }
                else              { l = __ldg((const float4*)rp); acc = l; }
                if (ny > 1) { l = __ldg((const float4*)(rp + HW));     f4add(acc, l); }
                if (ny > 2) { l = __ldg((const float4*)(rp + 2 * HW)); f4add(acc, l); }
                if (MAXTAP > 3 && ny > 3) {
                    l = __ldg((const float4*)(rp + 3 * HW)); f4add(acc, l);
                }
                *(float4*)&sm->buf[half * BPH + j][col4] = acc;
                last = l; pe = sy + ny;
            }
        } else if (rem > 0) {
            #pragma unroll
            for (int j = 0; j < BPH; j++) {
                const int m  = sm->syny[pg][half * BPH + j];
                const int sy = m & 0xFFFF;
                const int ny = m >> 16;
                const float* rp = pbase + (long long)sy * HW + col4;
                #pragma unroll
                for (int k = 0; k < 3; k++) {
                    if (k < rem) {
                        float s = __ldg(rp + k);
                        if (ny > 1) s += __ldg(rp + k + HW);
                        if (ny > 2) s += __ldg(rp + k + 2 * HW);
                        if (MAXTAP > 3 && ny > 3) s += __ldg(rp + k + 3 * HW);
                        sm->buf[half * BPH + j][col4 + k] = s;
                    }
                }
            }
        }
        if (span > 512 && tid == 126) {   // cols 512..514, rare
            #pragma unroll 1
            for (int j = 0; j < YG; j++) {
                const int m  = sm->syny[pg][j];
                const int sy = m & 0xFFFF;
                const int ny = m >> 16;
                for (int c = 512; c < span && c < 515; c++) {
                    const float* q = pbase + (long long)sy * HW + c;
                    float s = __ldg(q);
                    if (ny > 1) s += __ldg(q + HW);
                    if (ny > 2) s += __ldg(q + 2 * HW);
                    if (ny > 3) s += __ldg(q + 3 * HW);
                    sm->buf[j][c] = s;
                }
            }
        }
        __syncthreads();

        // ---- Phase 2: row pairs ----
        if (tid < OUTS) {
            long long oidx = obase + (long long)g * (YG * OUTS);
            #pragma unroll
            for (int i = 0; i < YG; i += 2) {
                const float* p0 = &sm->buf[i][off];
                const float* p1 = &sm->buf[i + 1][off];

                float s0 = p0[0], s1 = p1[0];
                float a0, a1, b0, b1, c0, c1;
                if (nx2) { a0 = p0[1]; a1 = p1[1]; }
                if (nx3) { b0 = p0[2]; b1 = p1[2]; }
                if (MAXTAP > 3 && nx4) { c0 = p0[3]; c1 = p1[3]; }
                if (nx2) { s0 += a0; s1 += a1; }
                if (nx3) { s0 += b0; s1 += b1; }
                if (MAXTAP > 3 && nx4) { s0 += c0; s1 += c1; }

                out[oidx]        = s0 * (invx * sm->invy[pg][i]);
                out[oidx + OUTS] = s1 * (invx * sm->invy[pg][i + 1]);
                oidx += 2 * OUTS;
            }
        }
    }
}

__global__ __launch_bounds__(256)
void makecutouts_v8(const float* __restrict__ x,
                    const int* __restrict__ sizes,
                    const int* __restrict__ offy,
                    const int* __restrict__ offx,
                    float* __restrict__ out)
{
    __shared__ Smem sm;

    const int tid = threadIdx.x;
    int bid = blockIdx.x;
    const int sg    = bid % NSG;  bid /= NSG;
    const int plane = bid % NPLANE;
    const int cut   = bid / NPLANE;

    const int sz = __ldg(sizes + cut);
    const int oy = __ldg(offy + cut);
    const int ox = __ldg(offx + cut);

    const int ox_al = ox & ~3;
    const int shift = ox - ox_al;
    const int span  = shift + sz;

    const float* pbase = x + (long long)plane * (HW * HW) + ox_al
                           + (long long)oy * HW;

    int sx = 0, nx = 1; float invx = 1.0f;
    if (tid < OUTS) {
        sx = (tid * sz) / OUTS;
        const int ex = ((tid + 1) * sz + (OUTS - 1)) / OUTS;
        nx = ex - sx;
        invx = inv_small(nx);
    }

    long long obase =
        ((long long)(cut * NPLANE + plane) * OUTS + sg * GPB * YG) * OUTS + tid;

    if (sz <= 448)
        run_groups<3>(&sm, pbase, out, sz, shift, span, sg, tid, sx, nx, invx, obase);
    else
        run_groups<4>(&sm, pbase, out, sz, shift, span, sg, tid, sx, nx, invx, obase);
}

extern "C" void kernel_launch(void* const* d_in, const int* in_sizes, int n_in,
                              void* d_out, int out_size)
{
    const float* x     = (const float*)d_in[0];
    const int*   sizes = (const int*)d_in[1];
    const int*   oy    = (const int*)d_in[2];
    const int*   ox    = (const int*)d_in[3];
    float* out = (float*)d_out;

    const int blocks = CUTN * NPLANE * NSG;   // 5376
    makecutouts_v8<<<blocks, 256>>>(x, sizes, oy, ox, out);
}